// round 14
// baseline (speedup 1.0000x reference)
#include <cuda_runtime.h>
#include <cuda_bf16.h>
#include <cstdint>

// Problem dims (fixed by the dataset)
#define TT 256
#define BB 1024
#define NROW (TT*BB)   // 262144

typedef unsigned long long u64;

// -------- device scratch (no allocations allowed) --------
__device__ __nv_bfloat16 g_hid_hi[(size_t)NROW * 128];  // encoder out, bf16 hi   64MB
__device__ __nv_bfloat16 g_hid_lo[(size_t)NROW * 128];  // encoder out, bf16 lo   64MB
__device__ float g_xg [(size_t)NROW * 512];             // x@Wih.T + bias        537MB
__device__ float g_hs [(size_t)NROW * 128];             // LSTM hidden states    134MB
__device__ float g_w1t [128 * 128];                     // W1 transposed [k][o]
__device__ float g_w2t [128 * 32];
__device__ float g_w3t [32 * 128];
__device__ __align__(16) float g_whead[19 * 128];       // [Wa;Wc]
__device__ float g_bhead[19];
__device__ float g_biasg[512];                          // bih + bhh
__device__ __nv_bfloat16 g_wbhi[512 * 128];             // Wih bf16 hi  [gate][k]
__device__ __nv_bfloat16 g_wblo[512 * 128];             // Wih bf16 lo  [gate][k]
__device__ __nv_bfloat16 g_whhbhi[512 * 128];           // Whh bf16 hi  [gate][k]
__device__ __nv_bfloat16 g_whhblo[512 * 128];           // Whh bf16 lo  [gate][k]

// -------- PTX helpers --------
__device__ __forceinline__ uint32_t smem_to_u32(const void* p) {
    uint32_t a;
    asm("{ .reg .u64 t; cvta.to.shared.u64 t, %1; cvt.u32.u64 %0, t; }" : "=r"(a) : "l"(p));
    return a;
}
__device__ __forceinline__ void ldsm4(uint32_t& r0, uint32_t& r1, uint32_t& r2, uint32_t& r3,
                                      uint32_t addr) {
    asm volatile("ldmatrix.sync.aligned.m8n8.x4.shared.b16 {%0,%1,%2,%3}, [%4];"
                 : "=r"(r0), "=r"(r1), "=r"(r2), "=r"(r3) : "r"(addr));
}
__device__ __forceinline__ void ldsm2(uint32_t& r0, uint32_t& r1, uint32_t addr) {
    asm volatile("ldmatrix.sync.aligned.m8n8.x2.shared.b16 {%0,%1}, [%2];"
                 : "=r"(r0), "=r"(r1) : "r"(addr));
}
__device__ __forceinline__ void mma16816(float* d, const uint32_t* a, const uint32_t* b) {
    asm volatile(
        "mma.sync.aligned.m16n8k16.row.col.f32.bf16.bf16.f32 "
        "{%0,%1,%2,%3},{%4,%5,%6,%7},{%8,%9},{%0,%1,%2,%3};"
        : "+f"(d[0]), "+f"(d[1]), "+f"(d[2]), "+f"(d[3])
        : "r"(a[0]), "r"(a[1]), "r"(a[2]), "r"(a[3]), "r"(b[0]), "r"(b[1]));
}

// -------- packed f32x2 helpers --------
__device__ __forceinline__ u64 pk2(float lo, float hi) {
    u64 r; asm("mov.b64 %0,{%1,%2};" : "=l"(r) : "f"(lo), "f"(hi)); return r;
}
__device__ __forceinline__ u64 dup2(float v) { return pk2(v, v); }
__device__ __forceinline__ void upk(u64 p, float& lo, float& hi) {
    asm("mov.b64 {%0,%1},%2;" : "=f"(lo), "=f"(hi) : "l"(p));
}
__device__ __forceinline__ u64 ffma2(u64 a, u64 b, u64 c) {
    u64 d; asm("fma.rn.f32x2 %0,%1,%2,%3;" : "=l"(d) : "l"(a), "l"(b), "l"(c)); return d;
}
// HW tanh (MUFU.TANH) — max rel err ~2^-11, 1 MUFU op
__device__ __forceinline__ float tanh_hw(float v) {
    float r; asm("tanh.approx.f32 %0, %1;" : "=f"(r) : "f"(v)); return r;
}
__device__ __forceinline__ float sig_hw(float v) {
    return fmaf(0.5f, tanh_hw(0.5f * v), 0.5f);
}

// -------- prep --------
__global__ void k_prep(const float* __restrict__ W1, const float* __restrict__ W2,
                       const float* __restrict__ W3, const float* __restrict__ Wih,
                       const float* __restrict__ Whh, const float* __restrict__ Wa,
                       const float* __restrict__ ba, const float* __restrict__ Wc,
                       const float* __restrict__ bc, const float* __restrict__ bih,
                       const float* __restrict__ bhh)
{
    int i0 = blockIdx.x * blockDim.x + threadIdx.x;
    int stride = gridDim.x * blockDim.x;
    for (int i = i0; i < 128*128; i += stride) { int k = i >> 7, o = i & 127; g_w1t[i] = W1[o*128 + k]; }
    for (int i = i0; i < 128*32;  i += stride) { int k = i / 32, o = i % 32;  g_w2t[i] = W2[o*128 + k]; }
    for (int i = i0; i < 32*128;  i += stride) { int k = i >> 7, o = i & 127; g_w3t[i] = W3[o*32  + k]; }
    for (int i = i0; i < 19*128;  i += stride) { int o = i >> 7, k = i & 127; g_whead[i] = (o < 18) ? Wa[o*128 + k] : Wc[k]; }
    for (int i = i0; i < 19;      i += stride) g_bhead[i] = (i < 18) ? ba[i] : bc[0];
    for (int i = i0; i < 512;     i += stride) g_biasg[i] = bih[i] + bhh[i];
    for (int i = i0; i < 512*128; i += stride) {
        float w = Wih[i];
        __nv_bfloat16 hb = __float2bfloat16(w);
        g_wbhi[i] = hb;
        g_wblo[i] = __float2bfloat16(w - __bfloat162float(hb));
        float v = Whh[i];
        __nv_bfloat16 vb = __float2bfloat16(v);
        g_whhbhi[i] = vb;
        g_whhblo[i] = __float2bfloat16(v - __bfloat162float(vb));
    }
}

// -------- fused 3-layer MLP encoder: 64 rows/block, 4 rows/thread --------
#define ENC_SMEM ((64*132 + 64*132 + 64*36) * 4)

__global__ void __launch_bounds__(256) k_enc(const float* __restrict__ x,
    const float* __restrict__ b1, const float* __restrict__ b2, const float* __restrict__ b3)
{
    extern __shared__ float es[];
    float* xs  = es;                  // [64][132]
    float* h1s = es + 64*132;         // [64][132]
    float* h2s = h1s + 64*132;        // [64][36]
    int tid = threadIdx.x;
    size_t row0 = (size_t)blockIdx.x * 64;
    for (int i = tid; i < 64*128; i += 256) { int r = i >> 7, k = i & 127; xs[r*132 + k] = x[(row0 + r)*128 + k]; }
    __syncthreads();
    int tx = tid & 15, ty = tid >> 4;
    int c0 = tx * 8, r0 = ty * 4;
    // stage 1: relu(x @ W1T + b1) -> h1s (4 rows per thread)
    {
        u64 acc[4][4];
        ulonglong2 bb0 = *(const ulonglong2*)&b1[c0];
        ulonglong2 bb1 = *(const ulonglong2*)&b1[c0 + 4];
        #pragma unroll
        for (int i = 0; i < 4; i++) { acc[i][0] = bb0.x; acc[i][1] = bb0.y; acc[i][2] = bb1.x; acc[i][3] = bb1.y; }
        #pragma unroll 4
        for (int k = 0; k < 128; k++) {
            ulonglong2 w0 = *(const ulonglong2*)&g_w1t[k*128 + c0];
            ulonglong2 w1 = *(const ulonglong2*)&g_w1t[k*128 + c0 + 4];
            #pragma unroll
            for (int i = 0; i < 4; i++) {
                u64 A = dup2(xs[(r0 + i)*132 + k]);
                acc[i][0] = ffma2(A, w0.x, acc[i][0]); acc[i][1] = ffma2(A, w0.y, acc[i][1]);
                acc[i][2] = ffma2(A, w1.x, acc[i][2]); acc[i][3] = ffma2(A, w1.y, acc[i][3]);
            }
        }
        #pragma unroll
        for (int i = 0; i < 4; i++)
            #pragma unroll
            for (int cp = 0; cp < 4; cp++) {
                float lo, hi; upk(acc[i][cp], lo, hi);
                h1s[(r0 + i)*132 + c0 + 2*cp]     = fmaxf(lo, 0.f);
                h1s[(r0 + i)*132 + c0 + 2*cp + 1] = fmaxf(hi, 0.f);
            }
    }
    __syncthreads();
    // stage 2: relu(h1 @ W2T + b2) -> h2s
    {
        int c = tx * 2;
        u64 acc[4];
        u64 bb = *(const u64*)&b2[c];
        #pragma unroll
        for (int i = 0; i < 4; i++) acc[i] = bb;
        #pragma unroll 4
        for (int k = 0; k < 128; k++) {
            u64 w = *(const u64*)&g_w2t[k*32 + c];
            #pragma unroll
            for (int i = 0; i < 4; i++) {
                u64 A = dup2(h1s[(r0 + i)*132 + k]);
                acc[i] = ffma2(A, w, acc[i]);
            }
        }
        #pragma unroll
        for (int i = 0; i < 4; i++) {
            float lo, hi; upk(acc[i], lo, hi);
            h2s[(r0 + i)*36 + c] = fmaxf(lo, 0.f);
            h2s[(r0 + i)*36 + c + 1] = fmaxf(hi, 0.f);
        }
    }
    __syncthreads();
    // stage 3: relu(h2 @ W3T + b3) -> bf16 hi/lo
    {
        u64 acc[4][4];
        ulonglong2 bb0 = *(const ulonglong2*)&b3[c0];
        ulonglong2 bb1 = *(const ulonglong2*)&b3[c0 + 4];
        #pragma unroll
        for (int i = 0; i < 4; i++) { acc[i][0] = bb0.x; acc[i][1] = bb0.y; acc[i][2] = bb1.x; acc[i][3] = bb1.y; }
        #pragma unroll
        for (int k = 0; k < 32; k++) {
            ulonglong2 w0 = *(const ulonglong2*)&g_w3t[k*128 + c0];
            ulonglong2 w1 = *(const ulonglong2*)&g_w3t[k*128 + c0 + 4];
            #pragma unroll
            for (int i = 0; i < 4; i++) {
                u64 A = dup2(h2s[(r0 + i)*36 + k]);
                acc[i][0] = ffma2(A, w0.x, acc[i][0]); acc[i][1] = ffma2(A, w0.y, acc[i][1]);
                acc[i][2] = ffma2(A, w1.x, acc[i][2]); acc[i][3] = ffma2(A, w1.y, acc[i][3]);
            }
        }
        #pragma unroll
        for (int i = 0; i < 4; i++) {
            __align__(16) __nv_bfloat16 hv[8];
            __align__(16) __nv_bfloat16 lv[8];
            #pragma unroll
            for (int cp = 0; cp < 4; cp++) {
                float lo, hi; upk(acc[i][cp], lo, hi);
                lo = fmaxf(lo, 0.f); hi = fmaxf(hi, 0.f);
                __nv_bfloat16 h0b = __float2bfloat16(lo);
                __nv_bfloat16 h1b = __float2bfloat16(hi);
                hv[2*cp]   = h0b; hv[2*cp+1] = h1b;
                lv[2*cp]   = __float2bfloat16(lo - __bfloat162float(h0b));
                lv[2*cp+1] = __float2bfloat16(hi - __bfloat162float(h1b));
            }
            size_t off = (row0 + r0 + i) * 128 + c0;
            *(uint4*)&g_hid_hi[off] = *(const uint4*)hv;
            *(uint4*)&g_hid_lo[off] = *(const uint4*)lv;
        }
    }
}

// -------- xg = hid @ WihT + bias via mma.sync bf16 hi/lo split --------
#define ASTR 136
#define XG_TILE_BYTES (128 * ASTR * 2)
#define XG_DYN_SMEM (4 * XG_TILE_BYTES + 512 + 16)

__global__ void __launch_bounds__(256) k_xgmma()
{
    extern __shared__ char dyn[];
    __nv_bfloat16* smb = (__nv_bfloat16*)dyn;
    float* sbias = (float*)(dyn + 4 * XG_TILE_BYTES);
    int tid = threadIdx.x;
    int wid = tid >> 5, lane = tid & 31;
    size_t row0 = (size_t)blockIdx.x * 128;
    int col0 = blockIdx.y * 128;

    for (int i = tid; i < 128 * 16; i += 256) {
        int r = i >> 4, v = i & 15;
        size_t goff = (row0 + r) * 128 + v * 8;
        int soff = r * ASTR + v * 8;
        *(uint4*)&smb[soff]              = *(const uint4*)&g_hid_hi[goff];
        *(uint4*)&smb[128*ASTR + soff]   = *(const uint4*)&g_hid_lo[goff];
        size_t woff = (size_t)(col0 + r) * 128 + v * 8;
        *(uint4*)&smb[2*128*ASTR + soff] = *(const uint4*)&g_wbhi[woff];
        *(uint4*)&smb[3*128*ASTR + soff] = *(const uint4*)&g_wblo[woff];
    }
    if (tid < 128) sbias[tid] = g_biasg[col0 + tid];
    __syncthreads();

    uint32_t smbase = smem_to_u32(smb);
    int wm = (wid & 3) * 32;
    int wn = (wid >> 2) * 64;
    int sub = lane >> 3, rowl = lane & 7;

    float acc[2][8][4];
    #pragma unroll
    for (int mt = 0; mt < 2; mt++)
        #pragma unroll
        for (int nt = 0; nt < 8; nt++)
            #pragma unroll
            for (int q = 0; q < 4; q++) acc[mt][nt][q] = 0.f;

    const uint32_t aBase[3] = {0u, 0u, (uint32_t)XG_TILE_BYTES};
    const uint32_t bBase[3] = {2u*XG_TILE_BYTES, 3u*XG_TILE_BYTES, 2u*XG_TILE_BYTES};

    int a_row_part = (sub & 1) * 8 + rowl;
    int a_col_part = (sub >> 1) * 8;
    int b_row_part = (sub >> 1) * 8 + rowl;
    int b_col_part = (sub & 1) * 8;

    #pragma unroll
    for (int pass = 0; pass < 3; pass++) {
        uint32_t aB = smbase + aBase[pass];
        uint32_t bB = smbase + bBase[pass];
        #pragma unroll
        for (int kc = 0; kc < 8; kc++) {
            uint32_t af[2][4];
            #pragma unroll
            for (int mt = 0; mt < 2; mt++) {
                uint32_t addr = aB + ((wm + mt*16 + a_row_part) * ASTR + kc*16 + a_col_part) * 2;
                ldsm4(af[mt][0], af[mt][1], af[mt][2], af[mt][3], addr);
            }
            uint32_t bf_[8][2];
            #pragma unroll
            for (int np = 0; np < 4; np++) {
                uint32_t addr = bB + ((wn + np*16 + b_row_part) * ASTR + kc*16 + b_col_part) * 2;
                uint32_t r0, r1, r2, r3;
                ldsm4(r0, r1, r2, r3, addr);
                bf_[np*2][0] = r0; bf_[np*2][1] = r1;
                bf_[np*2+1][0] = r2; bf_[np*2+1][1] = r3;
            }
            #pragma unroll
            for (int mt = 0; mt < 2; mt++)
                #pragma unroll
                for (int nt = 0; nt < 8; nt++)
                    mma16816(acc[mt][nt], af[mt], bf_[nt]);
        }
    }

    int g = lane >> 2, tg = lane & 3;
    #pragma unroll
    for (int mt = 0; mt < 2; mt++) {
        size_t r_top = row0 + wm + mt*16 + g;
        #pragma unroll
        for (int nt = 0; nt < 8; nt++) {
            int cl = wn + nt*8 + tg*2;
            float b0 = sbias[cl], b1 = sbias[cl + 1];
            float* o0 = &g_xg[r_top * 512 + col0 + cl];
            *(float2*)o0 = make_float2(acc[mt][nt][0] + b0, acc[mt][nt][1] + b1);
            float* o1 = &g_xg[(r_top + 8) * 512 + col0 + cl];
            *(float2*)o1 = make_float2(acc[mt][nt][2] + b0, acc[mt][nt][3] + b1);
        }
    }
}

// -------- LSTM recurrence on tensor cores: single sync/step, no fused head --------
// Warp w owns cells [8w, 8w+8). Per-lane accumulators hold i,f,g,o of ONE
// cell for 2 elems -> warp-local cell update. h written to g_hs (head kernel
// consumes it later). A-op (.x4) col-select = lane bit 4; B-op (.x2) = bit 3.
#define WSTR 136          // h row stride (bf16): 272B = 16*17, uint4-safe
#define W2STR 40          // whi tail row stride (bf16): 80B = 16*5, uint4-safe

struct __align__(16) Rec3 {
    __nv_bfloat16 wlo[512 * WSTR];     // 139264B (staging for hi at init, then lo)
    __nv_bfloat16 whi2[512 * W2STR];   // 40960B  (Whh_hi k 96..127)
    __nv_bfloat16 hhi[2][8 * WSTR];    // 4352B
    __nv_bfloat16 hlo[2][8 * WSTR];    // 4352B
};

__global__ void __launch_bounds__(512, 1) k_rec(const float* __restrict__ done,
    const float* __restrict__ h0, const float* __restrict__ c0)
{
    extern __shared__ char smraw[];
    Rec3& sm = *(Rec3*)smraw;
    int j = threadIdx.x;
    int wid = j >> 5, lane = j & 31;
    int base = blockIdx.x * 8;

    // ---- fill whi2 (k 96..127) directly from global ----
    for (int i = j; i < 512 * 4; i += 512) {
        int r = i >> 2, v = i & 3;
        *(uint4*)&sm.whi2[r * W2STR + v * 8] = *(const uint4*)&g_whhbhi[r * 128 + 96 + v * 8];
    }
    // ---- stage Whh_hi into wlo area ----
    for (int i = j; i < 512 * 16; i += 512) {
        int r = i >> 4, v = i & 15;
        *(uint4*)&sm.wlo[r * WSTR + v * 8] = *(const uint4*)&g_whhbhi[r * 128 + v * 8];
    }
    __syncthreads();

    // per-lane A row: cells 8w..8w+7; atom pair (i,f) for mt0, (g,o) for mt1
    int rowA = 8 * wid + (lane & 7) + ((lane >> 3) & 1) * 128;   // + mt*256
    int koff16 = ((lane >> 4) & 1) * 16;                          // A-op col sel (bit 4)
    int hoff16 = ((lane >> 3) & 1) * 16;                          // B-op col sel (bit 3)
    uint32_t wlo_u = smem_to_u32(sm.wlo);
    uint32_t wf[48];   // hi frags kt 0..5: [mt][kt][4]
    #pragma unroll
    for (int mt = 0; mt < 2; mt++) {
        uint32_t ab = wlo_u + (rowA + mt * 256) * (WSTR * 2) + koff16;
        #pragma unroll
        for (int kt = 0; kt < 6; kt++) {
            int o = (mt * 6 + kt) * 4;
            ldsm4(wf[o], wf[o+1], wf[o+2], wf[o+3], ab + kt * 32);
        }
    }
    __syncthreads();
    // ---- overwrite staging with Whh_lo ----
    for (int i = j; i < 512 * 16; i += 512) {
        int r = i >> 4, v = i & 15;
        *(uint4*)&sm.wlo[r * WSTR + v * 8] = *(const uint4*)&g_whhblo[r * 128 + v * 8];
    }

    // ---- per-lane state: cell cc, elems e0,e0+1 ----
    int cc = 8 * wid + (lane >> 2);
    int e0 = (lane & 3) * 2;
    float c2a = c0[(base + e0) * 128 + cc];
    float c2b = c0[(base + e0 + 1) * 128 + cc];
    float dm0 = 1.0f - done[base + e0];
    float dm1 = 1.0f - done[base + e0 + 1];

    // init h (pre-masked) into buffer 0 (threads 0-127: cell j, all elems)
    if (j < 128) {
        #pragma unroll
        for (int e = 0; e < 8; e++) {
            int b = base + e;
            float hn = h0[b*128 + j] * (1.0f - done[b]);
            __nv_bfloat16 hb = __float2bfloat16(hn);
            sm.hhi[0][e*WSTR + j] = hb;
            sm.hlo[0][e*WSTR + j] = __float2bfloat16(hn - __bfloat162float(hb));
        }
    }
    // xv prefetch for t=0
    float xva[8], xvb[8];
    {
        const float* xr = g_xg + (size_t)base * 512;
        #pragma unroll
        for (int q = 0; q < 4; q++) {
            int gp = cc + q * 128;
            xva[2*q]   = xr[(size_t)e0 * 512 + gp];
            xva[2*q+1] = xr[(size_t)(e0+1) * 512 + gp];
        }
    }
    __syncthreads();

    uint32_t hhi_u = smem_to_u32(sm.hhi) + (lane & 7) * (WSTR*2) + hoff16;
    uint32_t hlo_u = smem_to_u32(sm.hlo) + (lane & 7) * (WSTR*2) + hoff16;
    uint32_t whi2_u = smem_to_u32(sm.whi2);
    const int hbufB = 8 * WSTR * 2;

    for (int t = 0; t < TT; t++) {
        int cur = t & 1, nxt = cur ^ 1;
        // -- prefetch xg + done for t+1 (consumed next step) --
        float dn0, dn1;
        {
            int tn = (t + 1 < TT) ? (t + 1) : t;
            const float* xr = g_xg + ((size_t)tn * BB + base) * 512;
            #pragma unroll
            for (int q = 0; q < 4; q++) {
                int gp = cc + q * 128;
                xvb[2*q]   = xr[(size_t)e0 * 512 + gp];
                xvb[2*q+1] = xr[(size_t)(e0+1) * 512 + gp];
            }
            dn0 = 1.0f - done[(size_t)tn * BB + base + e0];
            dn1 = 1.0f - done[(size_t)tn * BB + base + e0 + 1];
        }
        // -- MMA: gates^T = Whh @ h^T, 3-pass hi/lo --
        float acc[2][4] = {{0.f,0.f,0.f,0.f},{0.f,0.f,0.f,0.f}};
        uint32_t hb_u = hhi_u + cur * hbufB;
        uint32_t hl_u = hlo_u + cur * hbufB;
        #pragma unroll
        for (int kt = 0; kt < 8; kt++) {
            uint32_t bh[2], bl[2];
            ldsm2(bh[0], bh[1], hb_u + kt * 32);
            ldsm2(bl[0], bl[1], hl_u + kt * 32);
            #pragma unroll
            for (int mt = 0; mt < 2; mt++) {
                uint32_t al[4];
                ldsm4(al[0], al[1], al[2], al[3],
                      wlo_u + (rowA + mt * 256) * (WSTR*2) + koff16 + kt * 32);
                if (kt < 6) {
                    const uint32_t* ah = &wf[(mt * 6 + kt) * 4];
                    mma16816(acc[mt], ah, bh);
                    mma16816(acc[mt], ah, bl);
                } else {
                    uint32_t ah[4];
                    ldsm4(ah[0], ah[1], ah[2], ah[3],
                          whi2_u + (rowA + mt * 256) * (W2STR*2) + koff16 + (kt - 6) * 32);
                    mma16816(acc[mt], ah, bh);
                    mma16816(acc[mt], ah, bl);
                }
                mma16816(acc[mt], al, bh);
            }
        }
        // -- gates + activations (HW tanh): acc0 = (i,f); acc1 = (g, o) --
        float iv0 = sig_hw(acc[0][0] + xva[0]), iv1 = sig_hw(acc[0][1] + xva[1]);
        float fv0 = sig_hw(acc[0][2] + xva[2]), fv1 = sig_hw(acc[0][3] + xva[3]);
        float gv0 = tanh_hw(acc[1][0] + xva[4]), gv1 = tanh_hw(acc[1][1] + xva[5]);
        float ov0 = sig_hw(acc[1][2] + xva[6]), ov1 = sig_hw(acc[1][3] + xva[7]);
        // -- warp-local cell update --
        c2a = fv0 * (c2a * dm0) + iv0 * gv0;
        c2b = fv1 * (c2b * dm1) + iv1 * gv1;
        float ha = ov0 * tanh_hw(c2a);
        float hb = ov1 * tanh_hw(c2b);
        // h -> global (head kernel consumes later); fire-and-forget
        size_t ho = ((size_t)t * BB + base + e0) * 128 + cc;
        g_hs[ho]       = ha;
        g_hs[ho + 128] = hb;
        float hna = ha * dn0, hnb = hb * dn1;
        __nv_bfloat16 hba = __float2bfloat16(hna);
        __nv_bfloat16 hbb = __float2bfloat16(hnb);
        sm.hhi[nxt][e0*WSTR + cc]     = hba;
        sm.hhi[nxt][(e0+1)*WSTR + cc] = hbb;
        sm.hlo[nxt][e0*WSTR + cc]     = __float2bfloat16(hna - __bfloat162float(hba));
        sm.hlo[nxt][(e0+1)*WSTR + cc] = __float2bfloat16(hnb - __bfloat162float(hbb));
        dm0 = dn0; dm1 = dn1;
        #pragma unroll
        for (int q = 0; q < 8; q++) xva[q] = xvb[q];
        __syncthreads();
    }
}

// -------- heads: out[r][0:18]=hs@WaT+ba, out[r][18]=hs@WcT+bc --------
__global__ void __launch_bounds__(256) k_head(float* __restrict__ out)
{
    __shared__ float hsx[64][132];
    __shared__ float wh[19][132];
    __shared__ float bh[19];
    int tid = threadIdx.x;
    size_t row0 = (size_t)blockIdx.x * 64;
    for (int i = tid; i < 64*128; i += 256) { int r = i >> 7, k = i & 127; hsx[r][k] = g_hs[(row0 + r)*128 + k]; }
    for (int i = tid; i < 19*128; i += 256) { int o = i >> 7, k = i & 127; wh[o][k] = g_whead[i]; }
    if (tid < 19) bh[tid] = g_bhead[tid];
    __syncthreads();
    for (int oi = tid; oi < 64*19; oi += 256) {
        int r = oi / 19, c = oi - r*19;
        float acc = bh[c];
        #pragma unroll
        for (int k = 0; k < 128; k += 4) {
            float4 a = *(const float4*)&hsx[r][k];
            float4 w = *(const float4*)&wh[c][k];
            acc += a.x*w.x + a.y*w.y + a.z*w.z + a.w*w.w;
        }
        out[(row0 + r)*19 + c] = acc;
    }
}

extern "C" void kernel_launch(void* const* d_in, const int* in_sizes, int n_in,
                              void* d_out, int out_size)
{
    const float* x    = (const float*)d_in[0];
    const float* done = (const float*)d_in[1];
    const float* h0   = (const float*)d_in[2];
    const float* c0   = (const float*)d_in[3];
    const float* W1   = (const float*)d_in[4];
    const float* b1   = (const float*)d_in[5];
    const float* W2   = (const float*)d_in[6];
    const float* b2   = (const float*)d_in[7];
    const float* W3   = (const float*)d_in[8];
    const float* b3   = (const float*)d_in[9];
    const float* Wih  = (const float*)d_in[10];
    const float* Whh  = (const float*)d_in[11];
    const float* bih  = (const float*)d_in[12];
    const float* bhh  = (const float*)d_in[13];
    const float* Wa   = (const float*)d_in[14];
    const float* ba   = (const float*)d_in[15];
    const float* Wc   = (const float*)d_in[16];
    const float* bc   = (const float*)d_in[17];

    int rec_smem = (int)sizeof(Rec3);
    cudaFuncSetAttribute(k_rec, cudaFuncAttributeMaxDynamicSharedMemorySize, rec_smem);
    cudaFuncSetAttribute(k_xgmma, cudaFuncAttributeMaxDynamicSharedMemorySize, XG_DYN_SMEM);
    cudaFuncSetAttribute(k_enc, cudaFuncAttributeMaxDynamicSharedMemorySize, ENC_SMEM);

    k_prep<<<256, 256>>>(W1, W2, W3, Wih, Whh, Wa, ba, Wc, bc, bih, bhh);
    k_enc<<<NROW/64, 256, ENC_SMEM>>>(x, b1, b2, b3);
    dim3 gmm(NROW/128, 4);
    k_xgmma<<<gmm, 256, XG_DYN_SMEM>>>();
    k_rec<<<128, 512, rec_smem>>>(done, h0, c0);
    k_head<<<NROW/64, 256>>>((float*)d_out);
}

// round 15
// speedup vs baseline: 1.5184x; 1.5184x over previous
#include <cuda_runtime.h>
#include <cuda_bf16.h>
#include <cstdint>

// Problem dims (fixed by the dataset)
#define TT 256
#define BB 1024
#define NROW (TT*BB)   // 262144

typedef unsigned long long u64;

// -------- device scratch (no allocations allowed) --------
__device__ __nv_bfloat16 g_hid_hi[(size_t)NROW * 128];  // encoder out, bf16 hi   64MB
__device__ __nv_bfloat16 g_hid_lo[(size_t)NROW * 128];  // encoder out, bf16 lo   64MB
__device__ float g_xg [(size_t)NROW * 512];             // x@Wih.T + bias        537MB
__device__ __align__(16) uint32_t g_hs32[(size_t)NROW * 128];  // h packed bf16 hi|lo<<16
__device__ float g_w1t [128 * 128];                     // W1 transposed [k][o]
__device__ float g_w2t [128 * 32];
__device__ float g_w3t [32 * 128];
__device__ float g_bhead[19];
__device__ float g_biasg[512];                          // bih + bhh
__device__ __nv_bfloat16 g_wbhi[512 * 128];             // Wih bf16 hi  [gate][k]
__device__ __nv_bfloat16 g_wblo[512 * 128];             // Wih bf16 lo  [gate][k]
__device__ __nv_bfloat16 g_whhbhi[512 * 128];           // Whh bf16 hi  [gate][k]
__device__ __nv_bfloat16 g_whhblo[512 * 128];           // Whh bf16 lo  [gate][k]
__device__ __nv_bfloat16 g_whbhi[24 * 128];             // head W bf16 hi (rows 19-23 zero)
__device__ __nv_bfloat16 g_whblo[24 * 128];             // head W bf16 lo

// -------- PTX helpers --------
__device__ __forceinline__ uint32_t smem_to_u32(const void* p) {
    uint32_t a;
    asm("{ .reg .u64 t; cvta.to.shared.u64 t, %1; cvt.u32.u64 %0, t; }" : "=r"(a) : "l"(p));
    return a;
}
__device__ __forceinline__ void ldsm4(uint32_t& r0, uint32_t& r1, uint32_t& r2, uint32_t& r3,
                                      uint32_t addr) {
    asm volatile("ldmatrix.sync.aligned.m8n8.x4.shared.b16 {%0,%1,%2,%3}, [%4];"
                 : "=r"(r0), "=r"(r1), "=r"(r2), "=r"(r3) : "r"(addr));
}
__device__ __forceinline__ void ldsm2(uint32_t& r0, uint32_t& r1, uint32_t addr) {
    asm volatile("ldmatrix.sync.aligned.m8n8.x2.shared.b16 {%0,%1}, [%2];"
                 : "=r"(r0), "=r"(r1) : "r"(addr));
}
__device__ __forceinline__ void mma16816(float* d, const uint32_t* a, const uint32_t* b) {
    asm volatile(
        "mma.sync.aligned.m16n8k16.row.col.f32.bf16.bf16.f32 "
        "{%0,%1,%2,%3},{%4,%5,%6,%7},{%8,%9},{%0,%1,%2,%3};"
        : "+f"(d[0]), "+f"(d[1]), "+f"(d[2]), "+f"(d[3])
        : "r"(a[0]), "r"(a[1]), "r"(a[2]), "r"(a[3]), "r"(b[0]), "r"(b[1]));
}

// -------- packed f32x2 helpers --------
__device__ __forceinline__ u64 pk2(float lo, float hi) {
    u64 r; asm("mov.b64 %0,{%1,%2};" : "=l"(r) : "f"(lo), "f"(hi)); return r;
}
__device__ __forceinline__ u64 dup2(float v) { return pk2(v, v); }
__device__ __forceinline__ void upk(u64 p, float& lo, float& hi) {
    asm("mov.b64 {%0,%1},%2;" : "=f"(lo), "=f"(hi) : "l"(p));
}
__device__ __forceinline__ u64 ffma2(u64 a, u64 b, u64 c) {
    u64 d; asm("fma.rn.f32x2 %0,%1,%2,%3;" : "=l"(d) : "l"(a), "l"(b), "l"(c)); return d;
}
// HW tanh (MUFU.TANH) — max rel err ~2^-11, 1 MUFU op
__device__ __forceinline__ float tanh_hw(float v) {
    float r; asm("tanh.approx.f32 %0, %1;" : "=f"(r) : "f"(v)); return r;
}
__device__ __forceinline__ float sig_hw(float v) {
    return fmaf(0.5f, tanh_hw(0.5f * v), 0.5f);
}
__device__ __forceinline__ uint32_t pack_hilo(float v) {
    __nv_bfloat16 h = __float2bfloat16(v);
    __nv_bfloat16 l = __float2bfloat16(v - __bfloat162float(h));
    return (uint32_t)__bfloat16_as_ushort(h) | ((uint32_t)__bfloat16_as_ushort(l) << 16);
}

// -------- prep --------
__global__ void k_prep(const float* __restrict__ W1, const float* __restrict__ W2,
                       const float* __restrict__ W3, const float* __restrict__ Wih,
                       const float* __restrict__ Whh, const float* __restrict__ Wa,
                       const float* __restrict__ ba, const float* __restrict__ Wc,
                       const float* __restrict__ bc, const float* __restrict__ bih,
                       const float* __restrict__ bhh)
{
    int i0 = blockIdx.x * blockDim.x + threadIdx.x;
    int stride = gridDim.x * blockDim.x;
    for (int i = i0; i < 128*128; i += stride) { int k = i >> 7, o = i & 127; g_w1t[i] = W1[o*128 + k]; }
    for (int i = i0; i < 128*32;  i += stride) { int k = i / 32, o = i % 32;  g_w2t[i] = W2[o*128 + k]; }
    for (int i = i0; i < 32*128;  i += stride) { int k = i >> 7, o = i & 127; g_w3t[i] = W3[o*32  + k]; }
    for (int i = i0; i < 19;      i += stride) g_bhead[i] = (i < 18) ? ba[i] : bc[0];
    for (int i = i0; i < 512;     i += stride) g_biasg[i] = bih[i] + bhh[i];
    for (int i = i0; i < 24*128;  i += stride) {
        int o = i >> 7, k = i & 127;
        float w = (o < 18) ? Wa[o*128 + k] : (o == 18 ? Wc[k] : 0.f);
        __nv_bfloat16 hb = __float2bfloat16(w);
        g_whbhi[i] = hb;
        g_whblo[i] = __float2bfloat16(w - __bfloat162float(hb));
    }
    for (int i = i0; i < 512*128; i += stride) {
        float w = Wih[i];
        __nv_bfloat16 hb = __float2bfloat16(w);
        g_wbhi[i] = hb;
        g_wblo[i] = __float2bfloat16(w - __bfloat162float(hb));
        float v = Whh[i];
        __nv_bfloat16 vb = __float2bfloat16(v);
        g_whhbhi[i] = vb;
        g_whhblo[i] = __float2bfloat16(v - __bfloat162float(vb));
    }
}

// -------- fused 3-layer MLP encoder: 64 rows/block, 4 rows/thread --------
#define ENC_SMEM ((64*132 + 64*132 + 64*36) * 4)

__global__ void __launch_bounds__(256) k_enc(const float* __restrict__ x,
    const float* __restrict__ b1, const float* __restrict__ b2, const float* __restrict__ b3)
{
    extern __shared__ float es[];
    float* xs  = es;                  // [64][132]
    float* h1s = es + 64*132;         // [64][132]
    float* h2s = h1s + 64*132;        // [64][36]
    int tid = threadIdx.x;
    size_t row0 = (size_t)blockIdx.x * 64;
    for (int i = tid; i < 64*128; i += 256) { int r = i >> 7, k = i & 127; xs[r*132 + k] = x[(row0 + r)*128 + k]; }
    __syncthreads();
    int tx = tid & 15, ty = tid >> 4;
    int c0 = tx * 8, r0 = ty * 4;
    // stage 1
    {
        u64 acc[4][4];
        ulonglong2 bb0 = *(const ulonglong2*)&b1[c0];
        ulonglong2 bb1 = *(const ulonglong2*)&b1[c0 + 4];
        #pragma unroll
        for (int i = 0; i < 4; i++) { acc[i][0] = bb0.x; acc[i][1] = bb0.y; acc[i][2] = bb1.x; acc[i][3] = bb1.y; }
        #pragma unroll 4
        for (int k = 0; k < 128; k++) {
            ulonglong2 w0 = *(const ulonglong2*)&g_w1t[k*128 + c0];
            ulonglong2 w1 = *(const ulonglong2*)&g_w1t[k*128 + c0 + 4];
            #pragma unroll
            for (int i = 0; i < 4; i++) {
                u64 A = dup2(xs[(r0 + i)*132 + k]);
                acc[i][0] = ffma2(A, w0.x, acc[i][0]); acc[i][1] = ffma2(A, w0.y, acc[i][1]);
                acc[i][2] = ffma2(A, w1.x, acc[i][2]); acc[i][3] = ffma2(A, w1.y, acc[i][3]);
            }
        }
        #pragma unroll
        for (int i = 0; i < 4; i++)
            #pragma unroll
            for (int cp = 0; cp < 4; cp++) {
                float lo, hi; upk(acc[i][cp], lo, hi);
                h1s[(r0 + i)*132 + c0 + 2*cp]     = fmaxf(lo, 0.f);
                h1s[(r0 + i)*132 + c0 + 2*cp + 1] = fmaxf(hi, 0.f);
            }
    }
    __syncthreads();
    // stage 2
    {
        int c = tx * 2;
        u64 acc[4];
        u64 bb = *(const u64*)&b2[c];
        #pragma unroll
        for (int i = 0; i < 4; i++) acc[i] = bb;
        #pragma unroll 4
        for (int k = 0; k < 128; k++) {
            u64 w = *(const u64*)&g_w2t[k*32 + c];
            #pragma unroll
            for (int i = 0; i < 4; i++) {
                u64 A = dup2(h1s[(r0 + i)*132 + k]);
                acc[i] = ffma2(A, w, acc[i]);
            }
        }
        #pragma unroll
        for (int i = 0; i < 4; i++) {
            float lo, hi; upk(acc[i], lo, hi);
            h2s[(r0 + i)*36 + c] = fmaxf(lo, 0.f);
            h2s[(r0 + i)*36 + c + 1] = fmaxf(hi, 0.f);
        }
    }
    __syncthreads();
    // stage 3 -> bf16 hi/lo
    {
        u64 acc[4][4];
        ulonglong2 bb0 = *(const ulonglong2*)&b3[c0];
        ulonglong2 bb1 = *(const ulonglong2*)&b3[c0 + 4];
        #pragma unroll
        for (int i = 0; i < 4; i++) { acc[i][0] = bb0.x; acc[i][1] = bb0.y; acc[i][2] = bb1.x; acc[i][3] = bb1.y; }
        #pragma unroll
        for (int k = 0; k < 32; k++) {
            ulonglong2 w0 = *(const ulonglong2*)&g_w3t[k*128 + c0];
            ulonglong2 w1 = *(const ulonglong2*)&g_w3t[k*128 + c0 + 4];
            #pragma unroll
            for (int i = 0; i < 4; i++) {
                u64 A = dup2(h2s[(r0 + i)*36 + k]);
                acc[i][0] = ffma2(A, w0.x, acc[i][0]); acc[i][1] = ffma2(A, w0.y, acc[i][1]);
                acc[i][2] = ffma2(A, w1.x, acc[i][2]); acc[i][3] = ffma2(A, w1.y, acc[i][3]);
            }
        }
        #pragma unroll
        for (int i = 0; i < 4; i++) {
            __align__(16) __nv_bfloat16 hv[8];
            __align__(16) __nv_bfloat16 lv[8];
            #pragma unroll
            for (int cp = 0; cp < 4; cp++) {
                float lo, hi; upk(acc[i][cp], lo, hi);
                lo = fmaxf(lo, 0.f); hi = fmaxf(hi, 0.f);
                __nv_bfloat16 h0b = __float2bfloat16(lo);
                __nv_bfloat16 h1b = __float2bfloat16(hi);
                hv[2*cp]   = h0b; hv[2*cp+1] = h1b;
                lv[2*cp]   = __float2bfloat16(lo - __bfloat162float(h0b));
                lv[2*cp+1] = __float2bfloat16(hi - __bfloat162float(h1b));
            }
            size_t off = (row0 + r0 + i) * 128 + c0;
            *(uint4*)&g_hid_hi[off] = *(const uint4*)hv;
            *(uint4*)&g_hid_lo[off] = *(const uint4*)lv;
        }
    }
}

// -------- xg = hid @ WihT + bias via mma.sync bf16 hi/lo split --------
#define ASTR 136
#define XG_TILE_BYTES (128 * ASTR * 2)
#define XG_DYN_SMEM (4 * XG_TILE_BYTES + 512 + 16)

__global__ void __launch_bounds__(256) k_xgmma()
{
    extern __shared__ char dyn[];
    __nv_bfloat16* smb = (__nv_bfloat16*)dyn;
    float* sbias = (float*)(dyn + 4 * XG_TILE_BYTES);
    int tid = threadIdx.x;
    int wid = tid >> 5, lane = tid & 31;
    size_t row0 = (size_t)blockIdx.x * 128;
    int col0 = blockIdx.y * 128;

    for (int i = tid; i < 128 * 16; i += 256) {
        int r = i >> 4, v = i & 15;
        size_t goff = (row0 + r) * 128 + v * 8;
        int soff = r * ASTR + v * 8;
        *(uint4*)&smb[soff]              = *(const uint4*)&g_hid_hi[goff];
        *(uint4*)&smb[128*ASTR + soff]   = *(const uint4*)&g_hid_lo[goff];
        size_t woff = (size_t)(col0 + r) * 128 + v * 8;
        *(uint4*)&smb[2*128*ASTR + soff] = *(const uint4*)&g_wbhi[woff];
        *(uint4*)&smb[3*128*ASTR + soff] = *(const uint4*)&g_wblo[woff];
    }
    if (tid < 128) sbias[tid] = g_biasg[col0 + tid];
    __syncthreads();

    uint32_t smbase = smem_to_u32(smb);
    int wm = (wid & 3) * 32;
    int wn = (wid >> 2) * 64;
    int sub = lane >> 3, rowl = lane & 7;

    float acc[2][8][4];
    #pragma unroll
    for (int mt = 0; mt < 2; mt++)
        #pragma unroll
        for (int nt = 0; nt < 8; nt++)
            #pragma unroll
            for (int q = 0; q < 4; q++) acc[mt][nt][q] = 0.f;

    const uint32_t aBase[3] = {0u, 0u, (uint32_t)XG_TILE_BYTES};
    const uint32_t bBase[3] = {2u*XG_TILE_BYTES, 3u*XG_TILE_BYTES, 2u*XG_TILE_BYTES};

    int a_row_part = (sub & 1) * 8 + rowl;
    int a_col_part = (sub >> 1) * 8;
    int b_row_part = (sub >> 1) * 8 + rowl;
    int b_col_part = (sub & 1) * 8;

    #pragma unroll
    for (int pass = 0; pass < 3; pass++) {
        uint32_t aB = smbase + aBase[pass];
        uint32_t bB = smbase + bBase[pass];
        #pragma unroll
        for (int kc = 0; kc < 8; kc++) {
            uint32_t af[2][4];
            #pragma unroll
            for (int mt = 0; mt < 2; mt++) {
                uint32_t addr = aB + ((wm + mt*16 + a_row_part) * ASTR + kc*16 + a_col_part) * 2;
                ldsm4(af[mt][0], af[mt][1], af[mt][2], af[mt][3], addr);
            }
            uint32_t bf_[8][2];
            #pragma unroll
            for (int np = 0; np < 4; np++) {
                uint32_t addr = bB + ((wn + np*16 + b_row_part) * ASTR + kc*16 + b_col_part) * 2;
                uint32_t r0, r1, r2, r3;
                ldsm4(r0, r1, r2, r3, addr);
                bf_[np*2][0] = r0; bf_[np*2][1] = r1;
                bf_[np*2+1][0] = r2; bf_[np*2+1][1] = r3;
            }
            #pragma unroll
            for (int mt = 0; mt < 2; mt++)
                #pragma unroll
                for (int nt = 0; nt < 8; nt++)
                    mma16816(acc[mt][nt], af[mt], bf_[nt]);
        }
    }

    int g = lane >> 2, tg = lane & 3;
    #pragma unroll
    for (int mt = 0; mt < 2; mt++) {
        size_t r_top = row0 + wm + mt*16 + g;
        #pragma unroll
        for (int nt = 0; nt < 8; nt++) {
            int cl = wn + nt*8 + tg*2;
            float b0 = sbias[cl], b1 = sbias[cl + 1];
            float* o0 = &g_xg[r_top * 512 + col0 + cl];
            *(float2*)o0 = make_float2(acc[mt][nt][0] + b0, acc[mt][nt][1] + b1);
            float* o1 = &g_xg[(r_top + 8) * 512 + col0 + cl];
            *(float2*)o1 = make_float2(acc[mt][nt][2] + b0, acc[mt][nt][3] + b1);
        }
    }
}

// -------- LSTM recurrence on tensor cores: single sync/step --------
// Warp w owns cells [8w, 8w+8). Per-lane accumulators hold i,f,g,o of ONE
// cell for 2 elems -> warp-local cell update. h packed bf16 hi/lo staged in
// smem hraw, flushed coalesced to g_hs32 next step. A-op col-sel = lane bit 4;
// B-op = bit 3.
#define WSTR 136          // h row stride (bf16): 272B = 16*17, uint4-safe
#define W2STR 40          // whi tail row stride (bf16): 80B = 16*5, uint4-safe

struct __align__(16) Rec3 {
    __nv_bfloat16 wlo[512 * WSTR];     // 139264B (staging for hi at init, then lo)
    __nv_bfloat16 whi2[512 * W2STR];   // 40960B  (Whh_hi k 96..127)
    __nv_bfloat16 hhi[2][8 * WSTR];    // 4352B
    __nv_bfloat16 hlo[2][8 * WSTR];    // 4352B
    uint32_t hraw[2][8 * 128];         // 8192B   (packed unmasked h, double buf)
};

__global__ void __launch_bounds__(512, 1) k_rec(const float* __restrict__ done,
    const float* __restrict__ h0, const float* __restrict__ c0)
{
    extern __shared__ char smraw[];
    Rec3& sm = *(Rec3*)smraw;
    int j = threadIdx.x;
    int wid = j >> 5, lane = j & 31;
    int base = blockIdx.x * 8;

    // ---- fill whi2 (k 96..127) ----
    for (int i = j; i < 512 * 4; i += 512) {
        int r = i >> 2, v = i & 3;
        *(uint4*)&sm.whi2[r * W2STR + v * 8] = *(const uint4*)&g_whhbhi[r * 128 + 96 + v * 8];
    }
    // ---- stage Whh_hi into wlo area ----
    for (int i = j; i < 512 * 16; i += 512) {
        int r = i >> 4, v = i & 15;
        *(uint4*)&sm.wlo[r * WSTR + v * 8] = *(const uint4*)&g_whhbhi[r * 128 + v * 8];
    }
    __syncthreads();

    int rowA = 8 * wid + (lane & 7) + ((lane >> 3) & 1) * 128;   // + mt*256
    int koff16 = ((lane >> 4) & 1) * 16;                          // A-op col sel (bit 4)
    int hoff16 = ((lane >> 3) & 1) * 16;                          // B-op col sel (bit 3)
    uint32_t wlo_u = smem_to_u32(sm.wlo);
    uint32_t wf[48];   // hi frags kt 0..5: [mt][kt][4]
    #pragma unroll
    for (int mt = 0; mt < 2; mt++) {
        uint32_t ab = wlo_u + (rowA + mt * 256) * (WSTR * 2) + koff16;
        #pragma unroll
        for (int kt = 0; kt < 6; kt++) {
            int o = (mt * 6 + kt) * 4;
            ldsm4(wf[o], wf[o+1], wf[o+2], wf[o+3], ab + kt * 32);
        }
    }
    __syncthreads();
    // ---- overwrite staging with Whh_lo ----
    for (int i = j; i < 512 * 16; i += 512) {
        int r = i >> 4, v = i & 15;
        *(uint4*)&sm.wlo[r * WSTR + v * 8] = *(const uint4*)&g_whhblo[r * 128 + v * 8];
    }

    // ---- per-lane state: cell cc, elems e0,e0+1 ----
    int cc = 8 * wid + (lane >> 2);
    int e0 = (lane & 3) * 2;
    float c2a = c0[(base + e0) * 128 + cc];
    float c2b = c0[(base + e0 + 1) * 128 + cc];
    float dm0 = 1.0f - done[base + e0];
    float dm1 = 1.0f - done[base + e0 + 1];

    if (j < 128) {
        #pragma unroll
        for (int e = 0; e < 8; e++) {
            int b = base + e;
            float hn = h0[b*128 + j] * (1.0f - done[b]);
            __nv_bfloat16 hb = __float2bfloat16(hn);
            sm.hhi[0][e*WSTR + j] = hb;
            sm.hlo[0][e*WSTR + j] = __float2bfloat16(hn - __bfloat162float(hb));
        }
    }
    float xva[8], xvb[8];
    {
        const float* xr = g_xg + (size_t)base * 512;
        #pragma unroll
        for (int q = 0; q < 4; q++) {
            int gp = cc + q * 128;
            xva[2*q]   = xr[(size_t)e0 * 512 + gp];
            xva[2*q+1] = xr[(size_t)(e0+1) * 512 + gp];
        }
    }
    __syncthreads();

    uint32_t hhi_u = smem_to_u32(sm.hhi) + (lane & 7) * (WSTR*2) + hoff16;
    uint32_t hlo_u = smem_to_u32(sm.hlo) + (lane & 7) * (WSTR*2) + hoff16;
    uint32_t whi2_u = smem_to_u32(sm.whi2);
    const int hbufB = 8 * WSTR * 2;

    for (int t = 0; t < TT; t++) {
        int cur = t & 1, nxt = cur ^ 1;
        // -- flush h(t-1) to global, fully coalesced (fire and forget) --
        if (t > 0 && j < 256) {
            uint4 v = *(const uint4*)&sm.hraw[nxt][j * 4];
            int e = j >> 5, ccw = (j * 4) & 127;
            *(uint4*)&g_hs32[((size_t)(t - 1) * BB + base + e) * 128 + ccw] = v;
        }
        // -- prefetch xg + done for t+1 --
        float dn0, dn1;
        {
            int tn = (t + 1 < TT) ? (t + 1) : t;
            const float* xr = g_xg + ((size_t)tn * BB + base) * 512;
            #pragma unroll
            for (int q = 0; q < 4; q++) {
                int gp = cc + q * 128;
                xvb[2*q]   = xr[(size_t)e0 * 512 + gp];
                xvb[2*q+1] = xr[(size_t)(e0+1) * 512 + gp];
            }
            dn0 = 1.0f - done[(size_t)tn * BB + base + e0];
            dn1 = 1.0f - done[(size_t)tn * BB + base + e0 + 1];
        }
        // -- MMA: gates^T = Whh @ h^T, 3-pass hi/lo --
        float acc[2][4] = {{0.f,0.f,0.f,0.f},{0.f,0.f,0.f,0.f}};
        uint32_t hb_u = hhi_u + cur * hbufB;
        uint32_t hl_u = hlo_u + cur * hbufB;
        #pragma unroll
        for (int kt = 0; kt < 8; kt++) {
            uint32_t bh[2], bl[2];
            ldsm2(bh[0], bh[1], hb_u + kt * 32);
            ldsm2(bl[0], bl[1], hl_u + kt * 32);
            #pragma unroll
            for (int mt = 0; mt < 2; mt++) {
                uint32_t al[4];
                ldsm4(al[0], al[1], al[2], al[3],
                      wlo_u + (rowA + mt * 256) * (WSTR*2) + koff16 + kt * 32);
                if (kt < 6) {
                    const uint32_t* ah = &wf[(mt * 6 + kt) * 4];
                    mma16816(acc[mt], ah, bh);
                    mma16816(acc[mt], ah, bl);
                } else {
                    uint32_t ah[4];
                    ldsm4(ah[0], ah[1], ah[2], ah[3],
                          whi2_u + (rowA + mt * 256) * (W2STR*2) + koff16 + (kt - 6) * 32);
                    mma16816(acc[mt], ah, bh);
                    mma16816(acc[mt], ah, bl);
                }
                mma16816(acc[mt], al, bh);
            }
        }
        // -- gates + activations (HW tanh) --
        float iv0 = sig_hw(acc[0][0] + xva[0]), iv1 = sig_hw(acc[0][1] + xva[1]);
        float fv0 = sig_hw(acc[0][2] + xva[2]), fv1 = sig_hw(acc[0][3] + xva[3]);
        float gv0 = tanh_hw(acc[1][0] + xva[4]), gv1 = tanh_hw(acc[1][1] + xva[5]);
        float ov0 = sig_hw(acc[1][2] + xva[6]), ov1 = sig_hw(acc[1][3] + xva[7]);
        // -- warp-local cell update --
        c2a = fv0 * (c2a * dm0) + iv0 * gv0;
        c2b = fv1 * (c2b * dm1) + iv1 * gv1;
        float ha = ov0 * tanh_hw(c2a);
        float hb = ov1 * tanh_hw(c2b);
        // unmasked h packed bf16 hi/lo -> hraw (head consumes via g_hs32)
        sm.hraw[cur][e0 * 128 + cc]       = pack_hilo(ha);
        sm.hraw[cur][(e0 + 1) * 128 + cc] = pack_hilo(hb);
        float hna = ha * dn0, hnb = hb * dn1;
        __nv_bfloat16 hba = __float2bfloat16(hna);
        __nv_bfloat16 hbb = __float2bfloat16(hnb);
        sm.hhi[nxt][e0*WSTR + cc]     = hba;
        sm.hhi[nxt][(e0+1)*WSTR + cc] = hbb;
        sm.hlo[nxt][e0*WSTR + cc]     = __float2bfloat16(hna - __bfloat162float(hba));
        sm.hlo[nxt][(e0+1)*WSTR + cc] = __float2bfloat16(hnb - __bfloat162float(hbb));
        dm0 = dn0; dm1 = dn1;
        #pragma unroll
        for (int q = 0; q < 8; q++) xva[q] = xvb[q];
        __syncthreads();
    }

    // ---- epilogue: flush h(TT-1) ----
    if (j < 256) {
        uint4 v = *(const uint4*)&sm.hraw[(TT - 1) & 1][j * 4];
        int e = j >> 5, ccw = (j * 4) & 127;
        *(uint4*)&g_hs32[((size_t)(TT - 1) * BB + base + e) * 128 + ccw] = v;
    }
}

// -------- head via mma.sync: out[128 rows][19] = h[128][128] @ Whead^T --------
// N padded to 24 (3 n8 tiles, cols 19-23 zero-weight, not written).
#define HSTR 136
#define HEAD_SMEM ((2*128*HSTR + 2*24*HSTR) * 2 + 128)

__global__ void __launch_bounds__(256) k_head(float* __restrict__ out)
{
    extern __shared__ char hsr[];
    __nv_bfloat16* s_hi = (__nv_bfloat16*)hsr;
    __nv_bfloat16* s_lo = s_hi + 128*HSTR;
    __nv_bfloat16* w_hi = s_lo + 128*HSTR;
    __nv_bfloat16* w_lo = w_hi + 24*HSTR;
    float* sbias = (float*)(w_lo + 24*HSTR);
    int tid = threadIdx.x, wid = tid >> 5, lane = tid & 31;
    size_t row0 = (size_t)blockIdx.x * 128;

    // unpack h hi/lo into separate bf16 tiles
    for (int i = tid; i < 128*32; i += 256) {
        int r = i >> 5, v = i & 31;
        uint4 w = *(const uint4*)&g_hs32[(row0 + r)*128 + v*4];
        uint32_t h01 = __byte_perm(w.x, w.y, 0x5410);
        uint32_t h23 = __byte_perm(w.z, w.w, 0x5410);
        uint32_t l01 = __byte_perm(w.x, w.y, 0x7632);
        uint32_t l23 = __byte_perm(w.z, w.w, 0x7632);
        *(uint2*)&s_hi[r*HSTR + v*4] = make_uint2(h01, h23);
        *(uint2*)&s_lo[r*HSTR + v*4] = make_uint2(l01, l23);
    }
    for (int i = tid; i < 24*16; i += 256) {
        int r = i >> 4, v = i & 15;
        *(uint4*)&w_hi[r*HSTR + v*8] = *(const uint4*)&g_whbhi[r*128 + v*8];
        *(uint4*)&w_lo[r*HSTR + v*8] = *(const uint4*)&g_whblo[r*128 + v*8];
    }
    if (tid < 19) sbias[tid] = g_bhead[tid];
    __syncthreads();

    uint32_t sHi_u = smem_to_u32(s_hi), sLo_u = smem_to_u32(s_lo);
    uint32_t wHi_u = smem_to_u32(w_hi), wLo_u = smem_to_u32(w_lo);
    int sub = lane >> 3, rowl = lane & 7;
    int aoff = ((wid*16 + (sub & 1)*8 + rowl) * HSTR + (sub >> 1)*8) * 2;
    int brow = lane & 7;
    int boff16 = ((lane >> 3) & 1) * 16;

    // B_hi fragments resident (3 nt x 8 kt x 2)
    uint32_t bh[3][8][2];
    #pragma unroll
    for (int nt = 0; nt < 3; nt++)
        #pragma unroll
        for (int kt = 0; kt < 8; kt++)
            ldsm2(bh[nt][kt][0], bh[nt][kt][1],
                  wHi_u + ((nt*8 + brow) * HSTR) * 2 + kt*32 + boff16);

    float acc[3][4] = {{0,0,0,0},{0,0,0,0},{0,0,0,0}};
    #pragma unroll
    for (int kt = 0; kt < 8; kt++) {
        uint32_t ah[4], al4[4];
        ldsm4(ah[0], ah[1], ah[2], ah[3], sHi_u + aoff + kt*32);
        ldsm4(al4[0], al4[1], al4[2], al4[3], sLo_u + aoff + kt*32);
        #pragma unroll
        for (int nt = 0; nt < 3; nt++) {
            uint32_t bl[2];
            ldsm2(bl[0], bl[1], wLo_u + ((nt*8 + brow) * HSTR) * 2 + kt*32 + boff16);
            mma16816(acc[nt], ah, bh[nt][kt]);
            mma16816(acc[nt], al4, bh[nt][kt]);
            mma16816(acc[nt], ah, bl);
        }
    }

    int g = lane >> 2, c2 = (lane & 3) * 2;
    size_t r_a = row0 + wid*16 + g;
    size_t r_b = r_a + 8;
    #pragma unroll
    for (int nt = 0; nt < 3; nt++) {
        int col = nt*8 + c2;
        if (col < 19) {
            float bv = sbias[col];
            out[r_a*19 + col] = acc[nt][0] + bv;
            out[r_b*19 + col] = acc[nt][2] + bv;
        }
        if (col + 1 < 19) {
            float bv = sbias[col + 1];
            out[r_a*19 + col + 1] = acc[nt][1] + bv;
            out[r_b*19 + col + 1] = acc[nt][3] + bv;
        }
    }
}

extern "C" void kernel_launch(void* const* d_in, const int* in_sizes, int n_in,
                              void* d_out, int out_size)
{
    const float* x    = (const float*)d_in[0];
    const float* done = (const float*)d_in[1];
    const float* h0   = (const float*)d_in[2];
    const float* c0   = (const float*)d_in[3];
    const float* W1   = (const float*)d_in[4];
    const float* b1   = (const float*)d_in[5];
    const float* W2   = (const float*)d_in[6];
    const float* b2   = (const float*)d_in[7];
    const float* W3   = (const float*)d_in[8];
    const float* b3   = (const float*)d_in[9];
    const float* Wih  = (const float*)d_in[10];
    const float* Whh  = (const float*)d_in[11];
    const float* bih  = (const float*)d_in[12];
    const float* bhh  = (const float*)d_in[13];
    const float* Wa   = (const float*)d_in[14];
    const float* ba   = (const float*)d_in[15];
    const float* Wc   = (const float*)d_in[16];
    const float* bc   = (const float*)d_in[17];

    int rec_smem = (int)sizeof(Rec3);
    cudaFuncSetAttribute(k_rec, cudaFuncAttributeMaxDynamicSharedMemorySize, rec_smem);
    cudaFuncSetAttribute(k_xgmma, cudaFuncAttributeMaxDynamicSharedMemorySize, XG_DYN_SMEM);
    cudaFuncSetAttribute(k_enc, cudaFuncAttributeMaxDynamicSharedMemorySize, ENC_SMEM);
    cudaFuncSetAttribute(k_head, cudaFuncAttributeMaxDynamicSharedMemorySize, HEAD_SMEM);

    k_prep<<<256, 256>>>(W1, W2, W3, Wih, Whh, Wa, ba, Wc, bc, bih, bhh);
    k_enc<<<NROW/64, 256, ENC_SMEM>>>(x, b1, b2, b3);
    dim3 gmm(NROW/128, 4);
    k_xgmma<<<gmm, 256, XG_DYN_SMEM>>>();
    k_rec<<<128, 512, rec_smem>>>(done, h0, c0);
    k_head<<<NROW/128, 256, HEAD_SMEM>>>((float*)d_out);
}